// round 6
// baseline (speedup 1.0000x reference)
#include <cuda_runtime.h>
#include <cuda_bf16.h>
#include <cstdint>

#define BATCH 32
#define SEQ   577
#define HEADS 12
#define HDIM  64
#define CDIM  768
#define MROWS (BATCH*SEQ)
#define QKVN  2304

__device__ float g_Q[(size_t)BATCH*HEADS*SEQ*HDIM];
__device__ float g_K[(size_t)BATCH*HEADS*SEQ*HDIM];
__device__ float g_V[(size_t)BATCH*HEADS*SEQ*HDIM];
__device__ __nv_bfloat16 g_xh[(size_t)MROWS*CDIM], g_xl[(size_t)MROWS*CDIM];
__device__ __nv_bfloat16 g_wqh[(size_t)QKVN*CDIM], g_wql[(size_t)QKVN*CDIM];
__device__ __nv_bfloat16 g_wph[(size_t)CDIM*CDIM], g_wpl[(size_t)CDIM*CDIM];
__device__ __nv_bfloat16 g_ah[(size_t)MROWS*CDIM], g_al[(size_t)MROWS*CDIM];

typedef unsigned long long u64t;

// ---------------- FFMA2 helpers (attention) ----------------
__device__ __forceinline__ void fma2(u64t& d, u64t a, u64t b) {
    asm("fma.rn.f32x2 %0, %1, %2, %0;" : "+l"(d) : "l"(a), "l"(b));
}
__device__ __forceinline__ void mul2(u64t& d, u64t a) {
    asm("mul.rn.f32x2 %0, %0, %1;" : "+l"(d) : "l"(a));
}
__device__ __forceinline__ u64t pack2(float lo, float hi) {
    u64t r; asm("mov.b64 %0, {%1, %2};" : "=l"(r) : "f"(lo), "f"(hi)); return r;
}
__device__ __forceinline__ u64t dup2(float x) { return pack2(x, x); }
__device__ __forceinline__ void unpack2(u64t p, float& lo, float& hi) {
    asm("mov.b64 {%0, %1}, %2;" : "=f"(lo), "=f"(hi) : "l"(p));
}
__device__ __forceinline__ void lds2(u64t& a, u64t& b, unsigned addr) {
    asm volatile("ld.shared.v2.u64 {%0, %1}, [%2];" : "=l"(a), "=l"(b) : "r"(addr));
}

// Fast exp on the FMA/ALU pipes (no MUFU). Valid for x <= ~80; clamps below -80.
__device__ __forceinline__ float fast_exp(float x) {
    float y = fmaxf(x, -80.f) * 1.44269504089f;      // log2(e)
    float z = y + 12582912.f;                        // 2^23 + 2^22: round-to-nearest
    int   i = __float_as_int(z);                     // low bits = integer part
    float f = y - (z - 12582912.f);                  // f in [-0.5, 0.5]
    // 2^f, degree-5 minimax (cephes coefficients)
    float p =             1.339887440266574e-3f;
    p = fmaf(p, f, 9.618437357674640e-3f);
    p = fmaf(p, f, 5.550332471162809e-2f);
    p = fmaf(p, f, 2.402264791363012e-1f);
    p = fmaf(p, f, 6.931472028550421e-1f);
    p = fmaf(p, f, 1.0f);
    return __int_as_float(__float_as_int(p) + (i << 23));
}

// ---------------- HMMA helpers ----------------
__device__ __forceinline__ void ldsm4(uint32_t* r, uint32_t addr) {
    asm volatile("ldmatrix.sync.aligned.m8n8.x4.shared.b16 {%0,%1,%2,%3}, [%4];"
        : "=r"(r[0]), "=r"(r[1]), "=r"(r[2]), "=r"(r[3]) : "r"(addr));
}
__device__ __forceinline__ void mma_bf16(float* c, const uint32_t* a, const uint32_t* b) {
    asm volatile("mma.sync.aligned.m16n8k16.row.col.f32.bf16.bf16.f32 "
        "{%0,%1,%2,%3}, {%4,%5,%6,%7}, {%8,%9}, {%0,%1,%2,%3};"
        : "+f"(c[0]), "+f"(c[1]), "+f"(c[2]), "+f"(c[3])
        : "r"(a[0]), "r"(a[1]), "r"(a[2]), "r"(a[3]), "r"(b[0]), "r"(b[1]));
}

// ---------------- fp32 -> bf16 hi/lo split kernels ----------------
__device__ __forceinline__ void cvt_body(const float* __restrict__ s,
                                         __nv_bfloat16* __restrict__ hi,
                                         __nv_bfloat16* __restrict__ lo) {
    size_t i = ((size_t)blockIdx.x * 256 + threadIdx.x) * 4;
    float4 v = *(const float4*)(s + i);
    float f[4] = {v.x, v.y, v.z, v.w};
    __nv_bfloat16 h[4], l[4];
    #pragma unroll
    for (int j = 0; j < 4; j++) {
        h[j] = __float2bfloat16(f[j]);
        l[j] = __float2bfloat16(f[j] - __bfloat162float(h[j]));
    }
    *(__nv_bfloat162*)(hi + i)     = *(__nv_bfloat162*)&h[0];
    *(__nv_bfloat162*)(hi + i + 2) = *(__nv_bfloat162*)&h[2];
    *(__nv_bfloat162*)(lo + i)     = *(__nv_bfloat162*)&l[0];
    *(__nv_bfloat162*)(lo + i + 2) = *(__nv_bfloat162*)&l[2];
}
__global__ __launch_bounds__(256) void cvt_x_kernel(const float* __restrict__ s)  { cvt_body(s, g_xh, g_xl); }
__global__ __launch_bounds__(256) void cvt_wq_kernel(const float* __restrict__ s) { cvt_body(s, g_wqh, g_wql); }
__global__ __launch_bounds__(256) void cvt_wp_kernel(const float* __restrict__ s) { cvt_body(s, g_wph, g_wpl); }

// ---------------- HMMA GEMM core: 128x128 tile, BK=32, 8 warps (64x32 each)
#define ROWB 80
#define OAH 0
#define OAL 10240
#define OBH 20480
#define OBL 30720
#define GEMM_SMEM 40960

__device__ __forceinline__ void mma_core(const __nv_bfloat16* __restrict__ Ah,
                                         const __nv_bfloat16* __restrict__ Al,
                                         const __nv_bfloat16* __restrict__ Bh,
                                         const __nv_bfloat16* __restrict__ Bl,
                                         int mBase, int nBase, float acc[4][4][4]) {
    extern __shared__ char smc[];
    const uint32_t su = (uint32_t)__cvta_generic_to_shared(smc);
    const int tid = threadIdx.x;
    const int lane = tid & 31, w = tid >> 5;
    const int wm = w & 1, wn = w >> 1;
    const int lrow = tid >> 1, lu = tid & 1;
    const bool aOk = (mBase + lrow) < MROWS;
    const __nv_bfloat16* pAh = Ah + (size_t)(mBase + lrow) * CDIM + lu * 16;
    const __nv_bfloat16* pAl = Al + (size_t)(mBase + lrow) * CDIM + lu * 16;
    const __nv_bfloat16* pBh = Bh + (size_t)(nBase + lrow) * CDIM + lu * 16;
    const __nv_bfloat16* pBl = Bl + (size_t)(nBase + lrow) * CDIM + lu * 16;
    const uint32_t stByte = (uint32_t)lrow * ROWB + (uint32_t)lu * 32;
    const uint32_t aRow = (uint32_t)(wm * 64 + (lane & 15));
    const uint32_t aKh  = (uint32_t)(lane >> 4);
    const uint32_t bRow = (uint32_t)(wn * 32 + ((lane >> 4) << 3) + (lane & 7));
    const uint32_t bKh  = (uint32_t)((lane >> 3) & 1);
    const uint4 z = make_uint4(0, 0, 0, 0);

    for (int t = 0; t < 24; t++) {
        const int k0 = t * 32;
        uint4 vah0 = aOk ? *(const uint4*)(pAh + k0) : z;
        uint4 vah1 = aOk ? *(const uint4*)(pAh + k0 + 8) : z;
        uint4 val0 = aOk ? *(const uint4*)(pAl + k0) : z;
        uint4 val1 = aOk ? *(const uint4*)(pAl + k0 + 8) : z;
        uint4 vbh0 = *(const uint4*)(pBh + k0);
        uint4 vbh1 = *(const uint4*)(pBh + k0 + 8);
        uint4 vbl0 = *(const uint4*)(pBl + k0);
        uint4 vbl1 = *(const uint4*)(pBl + k0 + 8);
        __syncthreads();
        *(uint4*)(smc + OAH + stByte) = vah0; *(uint4*)(smc + OAH + stByte + 16) = vah1;
        *(uint4*)(smc + OAL + stByte) = val0; *(uint4*)(smc + OAL + stByte + 16) = val1;
        *(uint4*)(smc + OBH + stByte) = vbh0; *(uint4*)(smc + OBH + stByte + 16) = vbh1;
        *(uint4*)(smc + OBL + stByte) = vbl0; *(uint4*)(smc + OBL + stByte + 16) = vbl1;
        __syncthreads();
        #pragma unroll
        for (int ks = 0; ks < 2; ks++) {
            const uint32_t kOff = (uint32_t)ks * 32;
            uint32_t af[4][4], bhf[4][2], blf[4][2];
            #pragma unroll
            for (int i = 0; i < 4; i++)
                ldsm4(af[i], su + OAH + (aRow + i*16)*ROWB + kOff + aKh*16);
            #pragma unroll
            for (int j2 = 0; j2 < 2; j2++) {
                uint32_t r[4];
                ldsm4(r, su + OBH + (bRow + j2*16)*ROWB + kOff + bKh*16);
                bhf[2*j2][0]=r[0]; bhf[2*j2][1]=r[1]; bhf[2*j2+1][0]=r[2]; bhf[2*j2+1][1]=r[3];
                ldsm4(r, su + OBL + (bRow + j2*16)*ROWB + kOff + bKh*16);
                blf[2*j2][0]=r[0]; blf[2*j2][1]=r[1]; blf[2*j2+1][0]=r[2]; blf[2*j2+1][1]=r[3];
            }
            #pragma unroll
            for (int i = 0; i < 4; i++)
                #pragma unroll
                for (int j = 0; j < 4; j++)
                    mma_bf16(acc[i][j], af[i], bhf[j]);
            #pragma unroll
            for (int i = 0; i < 4; i++)
                #pragma unroll
                for (int j = 0; j < 4; j++)
                    mma_bf16(acc[i][j], af[i], blf[j]);
            #pragma unroll
            for (int i = 0; i < 4; i++)
                ldsm4(af[i], su + OAL + (aRow + i*16)*ROWB + kOff + aKh*16);
            #pragma unroll
            for (int i = 0; i < 4; i++)
                #pragma unroll
                for (int j = 0; j < 4; j++)
                    mma_bf16(acc[i][j], af[i], bhf[j]);
        }
    }
}

__global__ __launch_bounds__(256, 2) void qkv_mma_kernel() {
    const int mBase = blockIdx.y * 128, nBase = blockIdx.x * 128;
    float acc[4][4][4];
    #pragma unroll
    for (int i = 0; i < 4; i++)
        #pragma unroll
        for (int j = 0; j < 4; j++)
            #pragma unroll
            for (int c = 0; c < 4; c++) acc[i][j][c] = 0.f;
    mma_core(g_xh, g_xl, g_wqh, g_wql, mBase, nBase, acc);

    const int lane = threadIdx.x & 31, w = threadIdx.x >> 5;
    const int wm = w & 1, wn = w >> 1;
    const int part = nBase / CDIM;
    float* dstb = (part == 0) ? g_Q : (part == 1) ? g_K : g_V;
    const int nOff = nBase - part * CDIM;
    #pragma unroll
    for (int i = 0; i < 4; i++) {
        const int m0 = mBase + wm*64 + i*16 + (lane >> 2);
        #pragma unroll
        for (int j = 0; j < 4; j++) {
            const int ncol = nOff + wn*32 + j*8 + (lane & 3)*2;
            const int hd = ncol >> 6, d0 = ncol & 63;
            if (m0 < MROWS) {
                int b = m0 / SEQ, q = m0 - b * SEQ;
                *(float2*)(dstb + ((size_t)(b*HEADS + hd)*SEQ + q)*HDIM + d0) =
                    make_float2(acc[i][j][0], acc[i][j][1]);
            }
            const int m1 = m0 + 8;
            if (m1 < MROWS) {
                int b = m1 / SEQ, q = m1 - b * SEQ;
                *(float2*)(dstb + ((size_t)(b*HEADS + hd)*SEQ + q)*HDIM + d0) =
                    make_float2(acc[i][j][2], acc[i][j][3]);
            }
        }
    }
}

__global__ __launch_bounds__(256, 2) void proj_mma_kernel(float* __restrict__ out,
                                                          const float* __restrict__ bias) {
    const int mBase = blockIdx.y * 128, nBase = blockIdx.x * 128;
    float acc[4][4][4];
    #pragma unroll
    for (int i = 0; i < 4; i++)
        #pragma unroll
        for (int j = 0; j < 4; j++)
            #pragma unroll
            for (int c = 0; c < 4; c++) acc[i][j][c] = 0.f;
    mma_core(g_ah, g_al, g_wph, g_wpl, mBase, nBase, acc);

    const int lane = threadIdx.x & 31, w = threadIdx.x >> 5;
    const int wm = w & 1, wn = w >> 1;
    #pragma unroll
    for (int i = 0; i < 4; i++) {
        const int m0 = mBase + wm*64 + i*16 + (lane >> 2);
        #pragma unroll
        for (int j = 0; j < 4; j++) {
            const int ncol = nBase + wn*32 + j*8 + (lane & 3)*2;
            const float2 bv = *(const float2*)(bias + ncol);
            if (m0 < MROWS)
                *(float2*)(out + (size_t)m0*CDIM + ncol) =
                    make_float2(acc[i][j][0] + bv.x, acc[i][j][1] + bv.y);
            const int m1 = m0 + 8;
            if (m1 < MROWS)
                *(float2*)(out + (size_t)m1*CDIM + ncol) =
                    make_float2(acc[i][j][2] + bv.x, acc[i][j][3] + bv.y);
        }
    }
}

// ---------------- Flash attention (FFMA2 + fast_exp), epilogue -> bf16 hi/lo
#define ATTN_SMEM_BYTES (25600*4)

__global__ __launch_bounds__(256, 2) void attn_kernel_fn() {
    extern __shared__ float smf[];
    float* Qs = smf;            // [d][r] stride 132 (scaled)
    float* Ks = smf + 8448;     // [d][c] stride 68
    float* Vs = smf + 12800;    // [c][d] stride 68
    float* Pt = smf + 17152;    // [c][r] stride 132
    const unsigned uSm = (unsigned)__cvta_generic_to_shared(smf);
    const unsigned uQ = uSm, uP = uSm + 17152*4;

    const int tid = threadIdx.x;
    const int tx = tid & 15, ty = tid >> 4;
    const int b = blockIdx.z, h = blockIdx.y;
    const int q0 = blockIdx.x * 128;
    const size_t base = (size_t)(b*HEADS + h) * SEQ * HDIM;
    const float* Qg = g_Q + base;
    const float* Kg = g_K + base;
    const float* Vg = g_V + base;
    const float4 z4 = make_float4(0.f,0.f,0.f,0.f);

    #pragma unroll
    for (int t = 0; t < 8; t++) {
        int lin = t*256 + tid;
        int r = lin >> 4;
        int d4 = (lin & 15) << 2;
        float4 v = (q0 + r < SEQ) ? *(const float4*)(Qg + (size_t)(q0+r)*HDIM + d4) : z4;
        Qs[(d4+0)*132 + r] = v.x * 0.125f;
        Qs[(d4+1)*132 + r] = v.y * 0.125f;
        Qs[(d4+2)*132 + r] = v.z * 0.125f;
        Qs[(d4+3)*132 + r] = v.w * 0.125f;
    }

    u64t op[4][4];
    #pragma unroll
    for (int p = 0; p < 4; p++)
        #pragma unroll
        for (int j = 0; j < 4; j++) op[p][j] = 0ull;
    float mi[8], li[8];
    #pragma unroll
    for (int i = 0; i < 8; i++) { mi[i] = -1e30f; li[i] = 0.f; }

    for (int kt = 0; kt < 10; kt++) {
        const int c0 = kt * 64;
        int nk = SEQ - c0; if (nk > 64) nk = 64;
        __syncthreads();
        #pragma unroll
        for (int t = 0; t < 4; t++) {
            int lin = t*256 + tid;
            int c = lin >> 4;
            int d4 = (lin & 15) << 2;
            float4 kv = z4, vv = z4;
            if (c < nk) {
                kv = *(const float4*)(Kg + (size_t)(c0+c)*HDIM + d4);
                vv = *(const float4*)(Vg + (size_t)(c0+c)*HDIM + d4);
            }
            Ks[(d4+0)*68 + c] = kv.x;
            Ks[(d4+1)*68 + c] = kv.y;
            Ks[(d4+2)*68 + c] = kv.z;
            Ks[(d4+3)*68 + c] = kv.w;
            *(float4*)(Vs + c*68 + d4) = vv;
        }
        __syncthreads();

        u64t sp[4][4];
        #pragma unroll
        for (int p = 0; p < 4; p++)
            #pragma unroll
            for (int j = 0; j < 4; j++) sp[p][j] = 0ull;
        #pragma unroll 4
        for (int d = 0; d < 64; d++) {
            u64t qp[4];
            lds2(qp[0], qp[1], uQ + (d*132 + 4*ty)*4);
            lds2(qp[2], qp[3], uQ + (d*132 + 64 + 4*ty)*4);
            float4 kf = *(const float4*)(Ks + d*68 + 4*tx);
            u64t kd[4] = {dup2(kf.x), dup2(kf.y), dup2(kf.z), dup2(kf.w)};
            #pragma unroll
            for (int p = 0; p < 4; p++)
                #pragma unroll
                for (int j = 0; j < 4; j++)
                    fma2(sp[p][j], qp[p], kd[j]);
        }

        float s8[8][4];
        #pragma unroll
        for (int p = 0; p < 4; p++)
            #pragma unroll
            for (int j = 0; j < 4; j++)
                unpack2(sp[p][j], s8[2*p][j], s8[2*p+1][j]);
        if (nk < 64) {
            #pragma unroll
            for (int j = 0; j < 4; j++)
                if (4*tx + j >= nk) {
                    #pragma unroll
                    for (int i = 0; i < 8; i++) s8[i][j] = -1e30f;
                }
        }

        float corr[8];
        #pragma unroll
        for (int i = 0; i < 8; i++) {
            float rm = fmaxf(fmaxf(s8[i][0], s8[i][1]), fmaxf(s8[i][2], s8[i][3]));
            #pragma unroll
            for (int off = 8; off > 0; off >>= 1)
                rm = fmaxf(rm, __shfl_xor_sync(0xffffffffu, rm, off));
            float mnew = fmaxf(mi[i], rm);
            corr[i] = fast_exp(mi[i] - mnew);
            float rs = 0.f;
            #pragma unroll
            for (int j = 0; j < 4; j++) { s8[i][j] = fast_exp(s8[i][j] - mnew); rs += s8[i][j]; }
            #pragma unroll
            for (int off = 8; off > 0; off >>= 1)
                rs += __shfl_xor_sync(0xffffffffu, rs, off);
            li[i] = li[i]*corr[i] + rs;
            mi[i] = mnew;
        }
        #pragma unroll
        for (int p = 0; p < 4; p++) {
            u64t cp = pack2(corr[2*p], corr[2*p+1]);
            #pragma unroll
            for (int j = 0; j < 4; j++) mul2(op[p][j], cp);
        }
        #pragma unroll
        for (int j = 0; j < 4; j++) {
            *(float4*)(Pt + (4*tx+j)*132 + 4*ty) =
                make_float4(s8[0][j], s8[1][j], s8[2][j], s8[3][j]);
            *(float4*)(Pt + (4*tx+j)*132 + 64 + 4*ty) =
                make_float4(s8[4][j], s8[5][j], s8[6][j], s8[7][j]);
        }
        __syncthreads();

        #pragma unroll 4
        for (int kk = 0; kk < 64; kk++) {
            u64t pp[4];
            lds2(pp[0], pp[1], uP + (kk*132 + 4*ty)*4);
            lds2(pp[2], pp[3], uP + (kk*132 + 64 + 4*ty)*4);
            float4 vf = *(const float4*)(Vs + kk*68 + 4*tx);
            u64t vd[4] = {dup2(vf.x), dup2(vf.y), dup2(vf.z), dup2(vf.w)};
            #pragma unroll
            for (int p = 0; p < 4; p++)
                #pragma unroll
                for (int j = 0; j < 4; j++)
                    fma2(op[p][j], pp[p], vd[j]);
        }
    }

    float o8[8][4];
    #pragma unroll
    for (int p = 0; p < 4; p++)
        #pragma unroll
        for (int j = 0; j < 4; j++)
            unpack2(op[p][j], o8[2*p][j], o8[2*p+1][j]);
    #pragma unroll
    for (int i = 0; i < 8; i++) {
        const int row = (i < 4) ? (4*ty + i) : (64 + 4*ty + i - 4);
        const int q = q0 + row;
        if (q < SEQ) {
            float inv = 1.0f / li[i];
            size_t idx = ((size_t)b*SEQ + q)*CDIM + h*HDIM + 4*tx;
            __nv_bfloat16 hh[4], ll[4];
            #pragma unroll
            for (int j = 0; j < 4; j++) {
                float f = o8[i][j] * inv;
                hh[j] = __float2bfloat16(f);
                ll[j] = __float2bfloat16(f - __bfloat162float(hh[j]));
            }
            *(__nv_bfloat162*)(g_ah + idx)     = *(__nv_bfloat162*)&hh[0];
            *(__nv_bfloat162*)(g_ah + idx + 2) = *(__nv_bfloat162*)&hh[2];
            *(__nv_bfloat162*)(g_al + idx)     = *(__nv_bfloat162*)&ll[0];
            *(__nv_bfloat162*)(g_al + idx + 2) = *(__nv_bfloat162*)&ll[2];
        }
    }
}

extern "C" void kernel_launch(void* const* d_in, const int* in_sizes, int n_in,
                              void* d_out, int out_size) {
    const float* x     = (const float*)d_in[0];
    const float* Wqkv  = (const float*)d_in[1];
    const float* Wproj = (const float*)d_in[2];
    const float* bproj = (const float*)d_in[3];
    float* out = (float*)d_out;
    (void)in_sizes; (void)n_in; (void)out_size;

    cudaFuncSetAttribute(attn_kernel_fn, cudaFuncAttributeMaxDynamicSharedMemorySize, ATTN_SMEM_BYTES);

    cvt_x_kernel <<<13848, 256>>>(x);
    cvt_wq_kernel<<<1728,  256>>>(Wqkv);
    cvt_wp_kernel<<<576,   256>>>(Wproj);
    qkv_mma_kernel<<<dim3(18, 145), 256, GEMM_SMEM>>>();
    attn_kernel_fn<<<dim3(5, HEADS, BATCH), 256, ATTN_SMEM_BYTES>>>();
    proj_mma_kernel<<<dim3(6, 145), 256, GEMM_SMEM>>>(out, bproj);
}

// round 8
// speedup vs baseline: 1.5349x; 1.5349x over previous
#include <cuda_runtime.h>
#include <cuda_bf16.h>
#include <cstdint>

#define BATCH 32
#define SEQ   577
#define HEADS 12
#define HDIM  64
#define CDIM  768
#define MROWS (BATCH*SEQ)
#define QKVN  2304

__device__ __nv_bfloat16 g_Qh[(size_t)BATCH*HEADS*SEQ*HDIM], g_Ql[(size_t)BATCH*HEADS*SEQ*HDIM];
__device__ __nv_bfloat16 g_Kh[(size_t)BATCH*HEADS*SEQ*HDIM], g_Kl[(size_t)BATCH*HEADS*SEQ*HDIM];
__device__ __nv_bfloat16 g_Vh[(size_t)BATCH*HEADS*SEQ*HDIM], g_Vl[(size_t)BATCH*HEADS*SEQ*HDIM];
__device__ __nv_bfloat16 g_xh[(size_t)MROWS*CDIM], g_xl[(size_t)MROWS*CDIM];
__device__ __nv_bfloat16 g_wqh[(size_t)QKVN*CDIM], g_wql[(size_t)QKVN*CDIM];
__device__ __nv_bfloat16 g_wph[(size_t)CDIM*CDIM], g_wpl[(size_t)CDIM*CDIM];
__device__ __nv_bfloat16 g_ah[(size_t)MROWS*CDIM], g_al[(size_t)MROWS*CDIM];

// ---------------- helpers ----------------
__device__ __forceinline__ void ldsm4(uint32_t* r, uint32_t addr) {
    asm volatile("ldmatrix.sync.aligned.m8n8.x4.shared.b16 {%0,%1,%2,%3}, [%4];"
        : "=r"(r[0]), "=r"(r[1]), "=r"(r[2]), "=r"(r[3]) : "r"(addr));
}
__device__ __forceinline__ void ldsm4t(uint32_t* r, uint32_t addr) {
    asm volatile("ldmatrix.sync.aligned.m8n8.x4.trans.shared.b16 {%0,%1,%2,%3}, [%4];"
        : "=r"(r[0]), "=r"(r[1]), "=r"(r[2]), "=r"(r[3]) : "r"(addr));
}
__device__ __forceinline__ void mma_bf16(float* c, const uint32_t* a, const uint32_t* b) {
    asm volatile("mma.sync.aligned.m16n8k16.row.col.f32.bf16.bf16.f32 "
        "{%0,%1,%2,%3}, {%4,%5,%6,%7}, {%8,%9}, {%0,%1,%2,%3};"
        : "+f"(c[0]), "+f"(c[1]), "+f"(c[2]), "+f"(c[3])
        : "r"(a[0]), "r"(a[1]), "r"(a[2]), "r"(a[3]), "r"(b[0]), "r"(b[1]));
}
// split a float pair into hi/lo bf16x2 words (element a -> low half)
__device__ __forceinline__ void split2(float a, float b, uint32_t& hi, uint32_t& lo) {
    __nv_bfloat16 ha = __float2bfloat16_rn(a);
    __nv_bfloat16 hb = __float2bfloat16_rn(b);
    __nv_bfloat162 h; h.x = ha; h.y = hb;
    hi = *(uint32_t*)&h;
    __nv_bfloat16 la = __float2bfloat16_rn(a - __bfloat162float(ha));
    __nv_bfloat16 lb = __float2bfloat16_rn(b - __bfloat162float(hb));
    __nv_bfloat162 l; l.x = la; l.y = lb;
    lo = *(uint32_t*)&l;
}

// ---------------- fp32 -> bf16 hi/lo split kernels ----------------
__device__ __forceinline__ void cvt_body(const float* __restrict__ s,
                                         __nv_bfloat16* __restrict__ hi,
                                         __nv_bfloat16* __restrict__ lo) {
    size_t i = ((size_t)blockIdx.x * 256 + threadIdx.x) * 4;
    float4 v = *(const float4*)(s + i);
    uint32_t h0, l0, h1, l1;
    split2(v.x, v.y, h0, l0);
    split2(v.z, v.w, h1, l1);
    *(uint32_t*)(hi + i) = h0; *(uint32_t*)(hi + i + 2) = h1;
    *(uint32_t*)(lo + i) = l0; *(uint32_t*)(lo + i + 2) = l1;
}
__global__ __launch_bounds__(256) void cvt_x_kernel(const float* __restrict__ s)  { cvt_body(s, g_xh, g_xl); }
__global__ __launch_bounds__(256) void cvt_wq_kernel(const float* __restrict__ s) { cvt_body(s, g_wqh, g_wql); }
__global__ __launch_bounds__(256) void cvt_wp_kernel(const float* __restrict__ s) { cvt_body(s, g_wph, g_wpl); }

// ---------------- HMMA GEMM core: 128x128 tile, BK=32, 8 warps (64x32 each)
#define ROWB 80
#define OAH 0
#define OAL 10240
#define OBH 20480
#define OBL 30720
#define GEMM_SMEM 40960

__device__ __forceinline__ void mma_core(const __nv_bfloat16* __restrict__ Ah,
                                         const __nv_bfloat16* __restrict__ Al,
                                         const __nv_bfloat16* __restrict__ Bh,
                                         const __nv_bfloat16* __restrict__ Bl,
                                         int mBase, int nBase, float acc[4][4][4]) {
    extern __shared__ char smc[];
    const uint32_t su = (uint32_t)__cvta_generic_to_shared(smc);
    const int tid = threadIdx.x;
    const int lane = tid & 31, w = tid >> 5;
    const int wm = w & 1, wn = w >> 1;
    const int lrow = tid >> 1, lu = tid & 1;
    const bool aOk = (mBase + lrow) < MROWS;
    const __nv_bfloat16* pAh = Ah + (size_t)(mBase + lrow) * CDIM + lu * 16;
    const __nv_bfloat16* pAl = Al + (size_t)(mBase + lrow) * CDIM + lu * 16;
    const __nv_bfloat16* pBh = Bh + (size_t)(nBase + lrow) * CDIM + lu * 16;
    const __nv_bfloat16* pBl = Bl + (size_t)(nBase + lrow) * CDIM + lu * 16;
    const uint32_t stByte = (uint32_t)lrow * ROWB + (uint32_t)lu * 32;
    const uint32_t aRow = (uint32_t)(wm * 64 + (lane & 15));
    const uint32_t aKh  = (uint32_t)(lane >> 4);
    const uint32_t bRow = (uint32_t)(wn * 32 + ((lane >> 4) << 3) + (lane & 7));
    const uint32_t bKh  = (uint32_t)((lane >> 3) & 1);
    const uint4 z = make_uint4(0, 0, 0, 0);

    for (int t = 0; t < 24; t++) {
        const int k0 = t * 32;
        uint4 vah0 = aOk ? *(const uint4*)(pAh + k0) : z;
        uint4 vah1 = aOk ? *(const uint4*)(pAh + k0 + 8) : z;
        uint4 val0 = aOk ? *(const uint4*)(pAl + k0) : z;
        uint4 val1 = aOk ? *(const uint4*)(pAl + k0 + 8) : z;
        uint4 vbh0 = *(const uint4*)(pBh + k0);
        uint4 vbh1 = *(const uint4*)(pBh + k0 + 8);
        uint4 vbl0 = *(const uint4*)(pBl + k0);
        uint4 vbl1 = *(const uint4*)(pBl + k0 + 8);
        __syncthreads();
        *(uint4*)(smc + OAH + stByte) = vah0; *(uint4*)(smc + OAH + stByte + 16) = vah1;
        *(uint4*)(smc + OAL + stByte) = val0; *(uint4*)(smc + OAL + stByte + 16) = val1;
        *(uint4*)(smc + OBH + stByte) = vbh0; *(uint4*)(smc + OBH + stByte + 16) = vbh1;
        *(uint4*)(smc + OBL + stByte) = vbl0; *(uint4*)(smc + OBL + stByte + 16) = vbl1;
        __syncthreads();
        #pragma unroll
        for (int ks = 0; ks < 2; ks++) {
            const uint32_t kOff = (uint32_t)ks * 32;
            uint32_t af[4][4], bhf[4][2], blf[4][2];
            #pragma unroll
            for (int i = 0; i < 4; i++)
                ldsm4(af[i], su + OAH + (aRow + i*16)*ROWB + kOff + aKh*16);
            #pragma unroll
            for (int j2 = 0; j2 < 2; j2++) {
                uint32_t r[4];
                ldsm4(r, su + OBH + (bRow + j2*16)*ROWB + kOff + bKh*16);
                bhf[2*j2][0]=r[0]; bhf[2*j2][1]=r[1]; bhf[2*j2+1][0]=r[2]; bhf[2*j2+1][1]=r[3];
                ldsm4(r, su + OBL + (bRow + j2*16)*ROWB + kOff + bKh*16);
                blf[2*j2][0]=r[0]; blf[2*j2][1]=r[1]; blf[2*j2+1][0]=r[2]; blf[2*j2+1][1]=r[3];
            }
            #pragma unroll
            for (int i = 0; i < 4; i++)
                #pragma unroll
                for (int j = 0; j < 4; j++)
                    mma_bf16(acc[i][j], af[i], bhf[j]);
            #pragma unroll
            for (int i = 0; i < 4; i++)
                #pragma unroll
                for (int j = 0; j < 4; j++)
                    mma_bf16(acc[i][j], af[i], blf[j]);
            #pragma unroll
            for (int i = 0; i < 4; i++)
                ldsm4(af[i], su + OAL + (aRow + i*16)*ROWB + kOff + aKh*16);
            #pragma unroll
            for (int i = 0; i < 4; i++)
                #pragma unroll
                for (int j = 0; j < 4; j++)
                    mma_bf16(acc[i][j], af[i], bhf[j]);
        }
    }
}

// qkv: epilogue emits bf16 hi/lo Q/K/V (Q pre-scaled by 1/8)
__global__ __launch_bounds__(256, 2) void qkv_mma_kernel() {
    const int mBase = blockIdx.y * 128, nBase = blockIdx.x * 128;
    float acc[4][4][4];
    #pragma unroll
    for (int i = 0; i < 4; i++)
        #pragma unroll
        for (int j = 0; j < 4; j++)
            #pragma unroll
            for (int c = 0; c < 4; c++) acc[i][j][c] = 0.f;
    mma_core(g_xh, g_xl, g_wqh, g_wql, mBase, nBase, acc);

    const int lane = threadIdx.x & 31, w = threadIdx.x >> 5;
    const int wm = w & 1, wn = w >> 1;
    const int part = nBase / CDIM;
    __nv_bfloat16* dsth = (part == 0) ? g_Qh : (part == 1) ? g_Kh : g_Vh;
    __nv_bfloat16* dstl = (part == 0) ? g_Ql : (part == 1) ? g_Kl : g_Vl;
    const float scale = (part == 0) ? 0.125f : 1.0f;
    const int nOff = nBase - part * CDIM;
    #pragma unroll
    for (int i = 0; i < 4; i++) {
        const int m0 = mBase + wm*64 + i*16 + (lane >> 2);
        #pragma unroll
        for (int j = 0; j < 4; j++) {
            const int ncol = nOff + wn*32 + j*8 + (lane & 3)*2;
            const int hd = ncol >> 6, d0 = ncol & 63;
            if (m0 < MROWS) {
                int b = m0 / SEQ, q = m0 - b * SEQ;
                size_t idx = ((size_t)(b*HEADS + hd)*SEQ + q)*HDIM + d0;
                uint32_t hi, lo;
                split2(acc[i][j][0]*scale, acc[i][j][1]*scale, hi, lo);
                *(uint32_t*)(dsth + idx) = hi; *(uint32_t*)(dstl + idx) = lo;
            }
            const int m1 = m0 + 8;
            if (m1 < MROWS) {
                int b = m1 / SEQ, q = m1 - b * SEQ;
                size_t idx = ((size_t)(b*HEADS + hd)*SEQ + q)*HDIM + d0;
                uint32_t hi, lo;
                split2(acc[i][j][2]*scale, acc[i][j][3]*scale, hi, lo);
                *(uint32_t*)(dsth + idx) = hi; *(uint32_t*)(dstl + idx) = lo;
            }
        }
    }
}

__global__ __launch_bounds__(256, 2) void proj_mma_kernel(float* __restrict__ out,
                                                          const float* __restrict__ bias) {
    const int mBase = blockIdx.y * 128, nBase = blockIdx.x * 128;
    float acc[4][4][4];
    #pragma unroll
    for (int i = 0; i < 4; i++)
        #pragma unroll
        for (int j = 0; j < 4; j++)
            #pragma unroll
            for (int c = 0; c < 4; c++) acc[i][j][c] = 0.f;
    mma_core(g_ah, g_al, g_wph, g_wpl, mBase, nBase, acc);

    const int lane = threadIdx.x & 31, w = threadIdx.x >> 5;
    const int wm = w & 1, wn = w >> 1;
    #pragma unroll
    for (int i = 0; i < 4; i++) {
        const int m0 = mBase + wm*64 + i*16 + (lane >> 2);
        #pragma unroll
        for (int j = 0; j < 4; j++) {
            const int ncol = nBase + wn*32 + j*8 + (lane & 3)*2;
            const float2 bv = *(const float2*)(bias + ncol);
            if (m0 < MROWS)
                *(float2*)(out + (size_t)m0*CDIM + ncol) =
                    make_float2(acc[i][j][0] + bv.x, acc[i][j][1] + bv.y);
            const int m1 = m0 + 8;
            if (m1 < MROWS)
                *(float2*)(out + (size_t)m1*CDIM + ncol) =
                    make_float2(acc[i][j][2] + bv.x, acc[i][j][3] + bv.y);
        }
    }
}

// ---------------- HMMA flash attention ----------------
// 128-q tile x 64-key tiles. 8 warps; warp w owns q rows 16w..16w+15.
// smem rows padded to 144 B -> ldmatrix conflict-free (bank = 4r + c).
#define AT_ROWB 144
#define AQH 0
#define AQL 18432
#define AKH 36864
#define AKL 46080
#define AVH 55296
#define AVL 64512
#define ATTN_SMEM 73728

__global__ __launch_bounds__(256, 2) void attn_kernel_fn() {
    extern __shared__ char smc[];
    const uint32_t su = (uint32_t)__cvta_generic_to_shared(smc);
    const int tid = threadIdx.x;
    const int lane = tid & 31, w = tid >> 5;
    const int b = blockIdx.z, h = blockIdx.y;
    const int q0 = blockIdx.x * 128;
    const size_t base = (size_t)(b*HEADS + h) * SEQ * HDIM;
    const uint4 z = make_uint4(0, 0, 0, 0);

    // Stage Q (hi/lo) once in dedicated smem
    #pragma unroll
    for (int t = 0; t < 4; t++) {
        int idx = t*256 + tid;
        int r = idx >> 3, c8 = (idx & 7) * 8;
        uint4 vh = z, vl = z;
        if (q0 + r < SEQ) {
            size_t g = base + (size_t)(q0 + r)*HDIM + c8;
            vh = *(const uint4*)(g_Qh + g);
            vl = *(const uint4*)(g_Ql + g);
        }
        *(uint4*)(smc + AQH + r*AT_ROWB + c8*2) = vh;
        *(uint4*)(smc + AQL + r*AT_ROWB + c8*2) = vl;
    }

    // fragment base offsets (bytes)
    const uint32_t aoff  = (uint32_t)((w*16 + (lane&7) + ((lane>>3)&1)*8) * AT_ROWB + ((lane>>4)&1)*16);
    const uint32_t boffK = (uint32_t)((((lane>>4)&1)*8 + (lane&7)) * AT_ROWB + ((lane>>3)&1)*16);
    const uint32_t boffV = (uint32_t)(((lane&7) + ((lane>>3)&1)*8) * AT_ROWB + ((lane>>4)&1)*16);

    float o[8][4];
    #pragma unroll
    for (int j = 0; j < 8; j++)
        #pragma unroll
        for (int c = 0; c < 4; c++) o[j][c] = 0.f;
    float mi0 = -1e30f, mi1 = -1e30f, li0 = 0.f, li1 = 0.f;

    for (int kt = 0; kt < 10; kt++) {
        const int c0 = kt * 64;
        const int nk = (SEQ - c0 < 64) ? (SEQ - c0) : 64;
        __syncthreads();
        #pragma unroll
        for (int t = 0; t < 2; t++) {
            int idx = t*256 + tid;
            int r = idx >> 3, c8 = (idx & 7) * 8;
            uint4 kh = z, kl = z, vh = z, vl = z;
            if (r < nk) {
                size_t g = base + (size_t)(c0 + r)*HDIM + c8;
                kh = *(const uint4*)(g_Kh + g); kl = *(const uint4*)(g_Kl + g);
                vh = *(const uint4*)(g_Vh + g); vl = *(const uint4*)(g_Vl + g);
            }
            uint32_t so = (uint32_t)(r*AT_ROWB + c8*2);
            *(uint4*)(smc + AKH + so) = kh; *(uint4*)(smc + AKL + so) = kl;
            *(uint4*)(smc + AVH + so) = vh; *(uint4*)(smc + AVL + so) = vl;
        }
        __syncthreads();

        // S = Qh*Kh + Ql*Kh + Qh*Kl
        float sc[8][4];
        #pragma unroll
        for (int j = 0; j < 8; j++)
            #pragma unroll
            for (int c = 0; c < 4; c++) sc[j][c] = 0.f;
        #pragma unroll
        for (int t = 0; t < 4; t++) {
            uint32_t kf[4][4], aq[4];
            #pragma unroll
            for (int j2 = 0; j2 < 4; j2++)
                ldsm4(kf[j2], su + AKH + boffK + (uint32_t)(j2*16*AT_ROWB) + t*32);
            ldsm4(aq, su + AQH + aoff + t*32);
            #pragma unroll
            for (int j2 = 0; j2 < 4; j2++) {
                mma_bf16(sc[2*j2],   aq, &kf[j2][0]);
                mma_bf16(sc[2*j2+1], aq, &kf[j2][2]);
            }
            ldsm4(aq, su + AQL + aoff + t*32);
            #pragma unroll
            for (int j2 = 0; j2 < 4; j2++) {
                mma_bf16(sc[2*j2],   aq, &kf[j2][0]);
                mma_bf16(sc[2*j2+1], aq, &kf[j2][2]);
            }
            #pragma unroll
            for (int j2 = 0; j2 < 4; j2++)
                ldsm4(kf[j2], su + AKL + boffK + (uint32_t)(j2*16*AT_ROWB) + t*32);
            ldsm4(aq, su + AQH + aoff + t*32);
            #pragma unroll
            for (int j2 = 0; j2 < 4; j2++) {
                mma_bf16(sc[2*j2],   aq, &kf[j2][0]);
                mma_bf16(sc[2*j2+1], aq, &kf[j2][2]);
            }
        }

        // mask tail keys
        if (nk < 64) {
            #pragma unroll
            for (int j = 0; j < 8; j++) {
                int col = 8*j + (lane & 3)*2;
                if (col   >= nk) { sc[j][0] = -1e30f; sc[j][2] = -1e30f; }
                if (col+1 >= nk) { sc[j][1] = -1e30f; sc[j][3] = -1e30f; }
            }
        }

        // online softmax (rows r0 = lane>>2, r1 = r0+8; quad-shfl reduce)
        float m0 = -1e30f, m1 = -1e30f;
        #pragma unroll
        for (int j = 0; j < 8; j++) {
            m0 = fmaxf(m0, fmaxf(sc[j][0], sc[j][1]));
            m1 = fmaxf(m1, fmaxf(sc[j][2], sc[j][3]));
        }
        m0 = fmaxf(m0, __shfl_xor_sync(0xffffffffu, m0, 1));
        m0 = fmaxf(m0, __shfl_xor_sync(0xffffffffu, m0, 2));
        m1 = fmaxf(m1, __shfl_xor_sync(0xffffffffu, m1, 1));
        m1 = fmaxf(m1, __shfl_xor_sync(0xffffffffu, m1, 2));
        float mn0 = fmaxf(mi0, m0), mn1 = fmaxf(mi1, m1);
        float cr0 = __expf(mi0 - mn0), cr1 = __expf(mi1 - mn1);
        float rs0 = 0.f, rs1 = 0.f;
        #pragma unroll
        for (int j = 0; j < 8; j++) {
            sc[j][0] = __expf(sc[j][0] - mn0); rs0 += sc[j][0];
            sc[j][1] = __expf(sc[j][1] - mn0); rs0 += sc[j][1];
            sc[j][2] = __expf(sc[j][2] - mn1); rs1 += sc[j][2];
            sc[j][3] = __expf(sc[j][3] - mn1); rs1 += sc[j][3];
        }
        rs0 += __shfl_xor_sync(0xffffffffu, rs0, 1);
        rs0 += __shfl_xor_sync(0xffffffffu, rs0, 2);
        rs1 += __shfl_xor_sync(0xffffffffu, rs1, 1);
        rs1 += __shfl_xor_sync(0xffffffffu, rs1, 2);
        li0 = li0*cr0 + rs0; li1 = li1*cr1 + rs1;
        mi0 = mn0; mi1 = mn1;
        #pragma unroll
        for (int j = 0; j < 8; j++) {
            o[j][0] *= cr0; o[j][1] *= cr0;
            o[j][2] *= cr1; o[j][3] *= cr1;
        }

        // O += P @ V  (Ph*Vh + Pl*Vh + Ph*Vl), V via ldmatrix.trans
        #pragma unroll
        for (int tk = 0; tk < 4; tk++) {
            uint32_t ah[4], al[4];
            split2(sc[2*tk][0],   sc[2*tk][1],   ah[0], al[0]);
            split2(sc[2*tk][2],   sc[2*tk][3],   ah[1], al[1]);
            split2(sc[2*tk+1][0], sc[2*tk+1][1], ah[2], al[2]);
            split2(sc[2*tk+1][2], sc[2*tk+1][3], ah[3], al[3]);
            #pragma unroll
            for (int j2 = 0; j2 < 4; j2++) {
                uint32_t vf[4];
                ldsm4t(vf, su + AVH + boffV + (uint32_t)(tk*16*AT_ROWB) + j2*32);
                mma_bf16(o[2*j2],   ah, &vf[0]);
                mma_bf16(o[2*j2+1], ah, &vf[2]);
                mma_bf16(o[2*j2],   al, &vf[0]);
                mma_bf16(o[2*j2+1], al, &vf[2]);
                ldsm4t(vf, su + AVL + boffV + (uint32_t)(tk*16*AT_ROWB) + j2*32);
                mma_bf16(o[2*j2],   ah, &vf[0]);
                mma_bf16(o[2*j2+1], ah, &vf[2]);
            }
        }
    }

    // epilogue: O/li -> bf16 hi/lo for proj GEMM
    float inv0 = 1.f / li0, inv1 = 1.f / li1;
    const int r0 = q0 + w*16 + (lane >> 2), r1 = r0 + 8;
    #pragma unroll
    for (int j = 0; j < 8; j++) {
        const int col = h*HDIM + 8*j + (lane & 3)*2;
        if (r0 < SEQ) {
            uint32_t hi, lo;
            split2(o[j][0]*inv0, o[j][1]*inv0, hi, lo);
            size_t idx = ((size_t)b*SEQ + r0)*CDIM + col;
            *(uint32_t*)(g_ah + idx) = hi; *(uint32_t*)(g_al + idx) = lo;
        }
        if (r1 < SEQ) {
            uint32_t hi, lo;
            split2(o[j][2]*inv1, o[j][3]*inv1, hi, lo);
            size_t idx = ((size_t)b*SEQ + r1)*CDIM + col;
            *(uint32_t*)(g_ah + idx) = hi; *(uint32_t*)(g_al + idx) = lo;
        }
    }
}

extern "C" void kernel_launch(void* const* d_in, const int* in_sizes, int n_in,
                              void* d_out, int out_size) {
    const float* x     = (const float*)d_in[0];
    const float* Wqkv  = (const float*)d_in[1];
    const float* Wproj = (const float*)d_in[2];
    const float* bproj = (const float*)d_in[3];
    float* out = (float*)d_out;
    (void)in_sizes; (void)n_in; (void)out_size;

    cudaFuncSetAttribute(attn_kernel_fn, cudaFuncAttributeMaxDynamicSharedMemorySize, ATTN_SMEM);

    cvt_x_kernel <<<13848, 256>>>(x);
    cvt_wq_kernel<<<1728,  256>>>(Wqkv);
    cvt_wp_kernel<<<576,   256>>>(Wproj);
    qkv_mma_kernel<<<dim3(18, 145), 256, GEMM_SMEM>>>();
    attn_kernel_fn<<<dim3(5, HEADS, BATCH), 256, ATTN_SMEM>>>();
    proj_mma_kernel<<<dim3(6, 145), 256, GEMM_SMEM>>>(out, bproj);
}